// round 3
// baseline (speedup 1.0000x reference)
#include <cuda_runtime.h>
#include <math.h>
#include <stdint.h>

// Problem dims (fixed for this dataset entry)
#define Bc 4
#define Tc 4096
#define Dc 1024
#define Hc 1024
#define BHc (Bc * Hc)        // 4096 chains
#define NCHUNK 32
#define CLEN (Tc / NCHUNK)   // 128 steps per chunk

// GEMM tiling
#define BM 128
#define BN 64
#define BK 16

// ---------------- scratch (static device globals; no allocs allowed) ------
__device__ float g_lc[(size_t)Bc * Tc * Hc];   // log_coeffs  [B,T,H]  64MB
__device__ float g_lv[(size_t)Bc * Tc * Hc];   // log_values  [B,T,H]  64MB
__device__ float g_A[NCHUNK * BHc];            // chunk coeff-sum
__device__ float g_R[NCHUNK * BHc];            // chunk value-reduce
__device__ float g_hin[NCHUNK * BHc];          // per-chunk entry state

typedef unsigned long long ull;

// ---------------- packed f32x2 helpers (sm_100+) ---------------------------
__device__ __forceinline__ ull pack2(float x, float y) {
    ull r; asm("mov.b64 %0, {%1, %2};" : "=l"(r) : "f"(x), "f"(y)); return r;
}
__device__ __forceinline__ float2 unpack2(ull v) {
    float2 r; asm("mov.b64 {%0, %1}, %2;" : "=f"(r.x), "=f"(r.y) : "l"(v)); return r;
}
__device__ __forceinline__ void fma2(ull &d, ull a, ull b) {
    asm("fma.rn.f32x2 %0, %1, %2, %0;" : "+l"(d) : "l"(a), "l"(b));
}

// ---------------- math helpers --------------------------------------------
__device__ __forceinline__ float softplus_f(float u) {
    // log(1 + e^u), stable
    return fmaxf(u, 0.f) + __logf(1.f + __expf(-fabsf(u)));
}
__device__ __forceinline__ float log_g_f(float v) {
    // log(g(v)): v>=0 -> log(v + 0.5), else log(sigmoid(v)) = -softplus(-v)
    return (v >= 0.f) ? __logf(v + 0.5f) : -softplus_f(-v);
}
__device__ __forceinline__ float logaddexp_f(float a, float b) {
    float m = fmaxf(a, b);
    if (m == -INFINITY) return -INFINITY;
    return m + __logf(1.f + __expf(-fabsf(a - b)));
}

// ===========================================================================
// Kernel 1: fused dual GEMM + log-space epilogue.
//   k  = x @ Wz^T + bz ;  hh = x @ Wh^T + bh
//   g_lc = -softplus(k)
//   g_lv = -softplus(-k) + log_g(hh)
// Block tile 128(M) x 64(N), 256 threads, micro-tile 8x4 per matrix,
// accumulators held as f32x2 pairs (pairs along N).
// ===========================================================================
__global__ void __launch_bounds__(256, 2) gemm_fused_kernel(
    const float* __restrict__ x,
    const float* __restrict__ Wz, const float* __restrict__ bz,
    const float* __restrict__ Wh, const float* __restrict__ bh)
{
    __shared__ float As[BK][BM];
    __shared__ float Bzs[BK][BN];
    __shared__ float Bhs[BK][BN];

    const int tid = threadIdx.x;
    const int tx = tid & 15;          // 0..15  -> N micro (4 cols)
    const int ty = tid >> 4;          // 0..15  -> M micro (8 rows)
    const int m0 = blockIdx.y * BM;
    const int n0 = blockIdx.x * BN;

    ull accz[8][2], acch[8][2];
#pragma unroll
    for (int i = 0; i < 8; i++) {
        accz[i][0] = 0ull; accz[i][1] = 0ull;
        acch[i][0] = 0ull; acch[i][1] = 0ull;
    }

    const float* xg = x + (size_t)m0 * Dc;

    for (int k0 = 0; k0 < Dc; k0 += BK) {
        // load x tile: 128x16, transposed into As[k][m]
#pragma unroll
        for (int i = 0; i < 2; i++) {
            int v = tid + i * 256;
            int r = v >> 2;
            int c = (v & 3) << 2;
            float4 t = *(const float4*)(xg + (size_t)r * Dc + k0 + c);
            As[c + 0][r] = t.x; As[c + 1][r] = t.y;
            As[c + 2][r] = t.z; As[c + 3][r] = t.w;
        }
        // load Wz/Wh tiles: 64x16 each, transposed
        {
            int r = tid >> 2;
            int c = (tid & 3) << 2;
            float4 t = *(const float4*)(Wz + (size_t)(n0 + r) * Dc + k0 + c);
            Bzs[c + 0][r] = t.x; Bzs[c + 1][r] = t.y;
            Bzs[c + 2][r] = t.z; Bzs[c + 3][r] = t.w;
            float4 u = *(const float4*)(Wh + (size_t)(n0 + r) * Dc + k0 + c);
            Bhs[c + 0][r] = u.x; Bhs[c + 1][r] = u.y;
            Bhs[c + 2][r] = u.z; Bhs[c + 3][r] = u.w;
        }
        __syncthreads();

#pragma unroll
        for (int k = 0; k < BK; k++) {
            float4 a03 = *(const float4*)&As[k][ty * 8];
            float4 a47 = *(const float4*)&As[k][ty * 8 + 4];
            ull as[8];
            as[0] = pack2(a03.x, a03.x); as[1] = pack2(a03.y, a03.y);
            as[2] = pack2(a03.z, a03.z); as[3] = pack2(a03.w, a03.w);
            as[4] = pack2(a47.x, a47.x); as[5] = pack2(a47.y, a47.y);
            as[6] = pack2(a47.z, a47.z); as[7] = pack2(a47.w, a47.w);

            float4 bzq = *(const float4*)&Bzs[k][tx * 4];
            float4 bhq = *(const float4*)&Bhs[k][tx * 4];
            ull bz01 = pack2(bzq.x, bzq.y), bz23 = pack2(bzq.z, bzq.w);
            ull bh01 = pack2(bhq.x, bhq.y), bh23 = pack2(bhq.z, bhq.w);

#pragma unroll
            for (int i = 0; i < 8; i++) {
                fma2(accz[i][0], as[i], bz01);
                fma2(accz[i][1], as[i], bz23);
                fma2(acch[i][0], as[i], bh01);
                fma2(acch[i][1], as[i], bh23);
            }
        }
        __syncthreads();
    }

    // epilogue: biases + log-space transforms, vectorized stores
    float bzl[4], bhl[4];
#pragma unroll
    for (int j = 0; j < 4; j++) {
        bzl[j] = bz[n0 + tx * 4 + j];
        bhl[j] = bh[n0 + tx * 4 + j];
    }
#pragma unroll
    for (int i = 0; i < 8; i++) {
        size_t row = (size_t)(m0 + ty * 8 + i);
        float2 z01 = unpack2(accz[i][0]), z23 = unpack2(accz[i][1]);
        float2 h01 = unpack2(acch[i][0]), h23 = unpack2(acch[i][1]);
        float kz[4] = { z01.x + bzl[0], z01.y + bzl[1], z23.x + bzl[2], z23.y + bzl[3] };
        float hh[4] = { h01.x + bhl[0], h01.y + bhl[1], h23.x + bhl[2], h23.y + bhl[3] };
        float4 lc4, lv4;
        lc4.x = -softplus_f(kz[0]); lc4.y = -softplus_f(kz[1]);
        lc4.z = -softplus_f(kz[2]); lc4.w = -softplus_f(kz[3]);
        lv4.x = -softplus_f(-kz[0]) + log_g_f(hh[0]);
        lv4.y = -softplus_f(-kz[1]) + log_g_f(hh[1]);
        lv4.z = -softplus_f(-kz[2]) + log_g_f(hh[2]);
        lv4.w = -softplus_f(-kz[3]) + log_g_f(hh[3]);
        size_t off = row * Hc + n0 + tx * 4;
        *(float4*)&g_lc[off] = lc4;
        *(float4*)&g_lv[off] = lv4;
    }
}

// ===========================================================================
// Scan phase 1: per-(chain, chunk) summaries.
//   State transform over a chunk:  h_out = e^A * h_in + e^R
//   A += lc ; R = logaddexp(R + lc, lv)
// thread g = chunk*BH + b*H + h  -> consecutive threads hit consecutive h
// ===========================================================================
__global__ void scan_chunks_kernel()
{
    int g = blockIdx.x * blockDim.x + threadIdx.x;
    int bh = g & (BHc - 1);
    int c  = g >> 12;                   // / 4096
    int b  = bh >> 10;
    int h  = bh & (Hc - 1);

    size_t base = ((size_t)b * Tc + (size_t)c * CLEN) * Hc + h;
    float A = 0.f;
    float R = -INFINITY;
#pragma unroll 4
    for (int t = 0; t < CLEN; t++) {
        float lc = g_lc[base];
        float lv = g_lv[base];
        base += Hc;
        R = logaddexp_f(R + lc, lv);
        A += lc;
    }
    g_A[g] = A;
    g_R[g] = R;
}

// ===========================================================================
// Scan phase 2: sequential combine across chunks (tiny: 4096 threads x 32)
// ===========================================================================
__global__ void scan_combine_kernel(const float* __restrict__ h0)
{
    int bh = blockIdx.x * blockDim.x + threadIdx.x;
    float lh = log_g_f(h0[bh]);        // h0 is [B,H] contiguous
#pragma unroll
    for (int c = 0; c < NCHUNK; c++) {
        int idx = c * BHc + bh;
        g_hin[idx] = lh;
        lh = logaddexp_f(g_A[idx] + lh, g_R[idx]);
    }
}

// ===========================================================================
// Scan phase 3: final pass, write exp(log_h) for t = 1..T (output [B,T,H])
// ===========================================================================
__global__ void scan_final_kernel(float* __restrict__ out)
{
    int g = blockIdx.x * blockDim.x + threadIdx.x;
    int bh = g & (BHc - 1);
    int c  = g >> 12;
    int b  = bh >> 10;
    int h  = bh & (Hc - 1);

    size_t base = ((size_t)b * Tc + (size_t)c * CLEN) * Hc + h;
    float lh = g_hin[g];
#pragma unroll 4
    for (int t = 0; t < CLEN; t++) {
        float lc = g_lc[base];
        float lv = g_lv[base];
        lh = logaddexp_f(lh + lc, lv);
        out[base] = __expf(lh);
        base += Hc;
    }
}

// ===========================================================================
extern "C" void kernel_launch(void* const* d_in, const int* in_sizes, int n_in,
                              void* d_out, int out_size)
{
    const float* x  = (const float*)d_in[0];
    const float* h0 = (const float*)d_in[1];
    const float* Wz = (const float*)d_in[2];
    const float* bz = (const float*)d_in[3];
    const float* Wh = (const float*)d_in[4];
    const float* bh = (const float*)d_in[5];
    float* out = (float*)d_out;

    dim3 ggrid(Hc / BN, (Bc * Tc) / BM);   // (16, 128)
    gemm_fused_kernel<<<ggrid, 256>>>(x, Wz, bz, Wh, bh);

    scan_chunks_kernel<<<(NCHUNK * BHc) / 256, 256>>>();
    scan_combine_kernel<<<BHc / 256, 256>>>(h0);
    scan_final_kernel<<<(NCHUNK * BHc) / 256, 256>>>(out);
}

// round 6
// speedup vs baseline: 2.1866x; 2.1866x over previous
#include <cuda_runtime.h>
#include <cuda_bf16.h>
#include <math.h>
#include <stdint.h>

// ---------------- problem dims -------------------------------------------
#define Bc 4
#define Tc 4096
#define Dc 1024
#define Hc 1024
#define BHc (Bc * Hc)
#define NCHUNK 64
#define CLEN (Tc / NCHUNK)       // 64

// ---------------- GEMM geometry ------------------------------------------
// CTA tile: 128(M) x 256(N), K tile 64 (bf16). N rows are interleaved
// [Wz 32 | Wh 32] blocks so each warp owns matching k / h~ columns.
#define BM 128
#define BN 256
#define NTILES 48                // K_total = 3072: hi*hi | lo*hi | hi*lo
#define STAGES 3
#define A_BYTES (BM * 128)       // 16384
#define B_BYTES (BN * 128)       // 32768
#define STAGE_BYTES (A_BYTES + B_BYTES)   // 49152
#define SMEM_TOTAL (STAGES * STAGE_BYTES) // 147456

// ---------------- scratch globals ----------------------------------------
__device__ __align__(1024) __nv_bfloat16 gx_hi[(size_t)Bc * Tc * Dc];
__device__ __align__(1024) __nv_bfloat16 gx_lo[(size_t)Bc * Tc * Dc];
__device__ __align__(1024) __nv_bfloat16 gw_hi[2048 * 1024];   // [Wz;Wh]
__device__ __align__(1024) __nv_bfloat16 gw_lo[2048 * 1024];
__device__ float2 g_lcv[(size_t)Bc * Tc * Hc];                 // (lc, lv)
__device__ float g_A[NCHUNK * BHc];
__device__ float g_R[NCHUNK * BHc];
__device__ float g_hin[NCHUNK * BHc];

// ---------------- PTX helpers --------------------------------------------
__device__ __forceinline__ uint32_t smem_u32(const void* p) {
    uint32_t a;
    asm("{ .reg .u64 t; cvta.to.shared.u64 t, %1; cvt.u32.u64 %0, t; }"
        : "=r"(a) : "l"(p));
    return a;
}
__device__ __forceinline__ void cp_async16(uint32_t dst, const void* src) {
    asm volatile("cp.async.cg.shared.global [%0], [%1], 16;"
                 :: "r"(dst), "l"(src) : "memory");
}
#define CP_COMMIT() asm volatile("cp.async.commit_group;" ::: "memory")
#define CP_WAIT2()  asm volatile("cp.async.wait_group 2;" ::: "memory")

#define LDSM_X4(r0, r1, r2, r3, addr) \
    asm volatile("ldmatrix.sync.aligned.m8n8.x4.shared.b16 {%0,%1,%2,%3}, [%4];" \
                 : "=r"(r0), "=r"(r1), "=r"(r2), "=r"(r3) : "r"(addr))

__device__ __forceinline__ void mma_bf16(float* c, const uint32_t* a,
                                         const uint32_t* b) {
    asm volatile(
        "mma.sync.aligned.m16n8k16.row.col.f32.bf16.bf16.f32 "
        "{%0,%1,%2,%3}, {%4,%5,%6,%7}, {%8,%9}, {%0,%1,%2,%3};"
        : "+f"(c[0]), "+f"(c[1]), "+f"(c[2]), "+f"(c[3])
        : "r"(a[0]), "r"(a[1]), "r"(a[2]), "r"(a[3]), "r"(b[0]), "r"(b[1]));
}

// ---------------- math helpers -------------------------------------------
__device__ __forceinline__ float softplus_f(float u) {
    return fmaxf(u, 0.f) + __logf(1.f + __expf(-fabsf(u)));
}
__device__ __forceinline__ float log_g_f(float v) {
    return (v >= 0.f) ? __logf(v + 0.5f) : -softplus_f(-v);
}
__device__ __forceinline__ float logaddexp_f(float a, float b) {
    float m = fmaxf(a, b);
    if (m == -INFINITY) return -INFINITY;
    return m + __logf(1.f + __expf(-fabsf(a - b)));
}

// ===========================================================================
// bf16 split kernels
// ===========================================================================
__global__ void split_x_kernel(const float4* __restrict__ x)
{
    size_t i = (size_t)blockIdx.x * blockDim.x + threadIdx.x;  // < 4194304
    float4 v = x[i];
    union { __nv_bfloat16 b[4]; uint2 u; } ph, pl;
    ph.b[0] = __float2bfloat16_rn(v.x); ph.b[1] = __float2bfloat16_rn(v.y);
    ph.b[2] = __float2bfloat16_rn(v.z); ph.b[3] = __float2bfloat16_rn(v.w);
    pl.b[0] = __float2bfloat16_rn(v.x - __bfloat162float(ph.b[0]));
    pl.b[1] = __float2bfloat16_rn(v.y - __bfloat162float(ph.b[1]));
    pl.b[2] = __float2bfloat16_rn(v.z - __bfloat162float(ph.b[2]));
    pl.b[3] = __float2bfloat16_rn(v.w - __bfloat162float(ph.b[3]));
    ((uint2*)gx_hi)[i] = ph.u;
    ((uint2*)gx_lo)[i] = pl.u;
}

__global__ void split_w_kernel(const float4* __restrict__ Wz,
                               const float4* __restrict__ Wh)
{
    int i = blockIdx.x * blockDim.x + threadIdx.x;   // < 524288
    const float4* src = (i < 262144) ? Wz : Wh;
    float4 v = src[(i < 262144) ? i : (i - 262144)];
    union { __nv_bfloat16 b[4]; uint2 u; } ph, pl;
    ph.b[0] = __float2bfloat16_rn(v.x); ph.b[1] = __float2bfloat16_rn(v.y);
    ph.b[2] = __float2bfloat16_rn(v.z); ph.b[3] = __float2bfloat16_rn(v.w);
    pl.b[0] = __float2bfloat16_rn(v.x - __bfloat162float(ph.b[0]));
    pl.b[1] = __float2bfloat16_rn(v.y - __bfloat162float(ph.b[1]));
    pl.b[2] = __float2bfloat16_rn(v.z - __bfloat162float(ph.b[2]));
    pl.b[3] = __float2bfloat16_rn(v.w - __bfloat162float(ph.b[3]));
    ((uint2*)gw_hi)[i] = ph.u;
    ((uint2*)gw_lo)[i] = pl.u;
}

// ===========================================================================
// HMMA GEMM + fused log-space epilogue.
// B-tile row r (0..255): j = r>>6 selects the warp-column's 32-wide h block,
// w = r&63: w<32 -> Wz row (n0*128 + j*32 + w), w>=32 -> Wh row (same h).
// So warp (wid&3)=j holds k in n8-tiles 0..3 and h~ in tiles 4..7 for
// identical (m, h) coordinates -> epilogue is fully in-register.
// ===========================================================================
__device__ __forceinline__ void load_tile(
    int kt, uint32_t sbase, int m0, int n0, int tid)
{
    int phase = kt >> 4;
    int kk = (kt & 15) << 6;
    const __nv_bfloat16* A = (phase == 1) ? gx_lo : gx_hi;
    const __nv_bfloat16* B = (phase == 2) ? gw_lo : gw_hi;
    uint32_t bB = sbase + A_BYTES;
#pragma unroll
    for (int i = 0; i < 4; i++) {           // A: 128 rows x 8 chunks
        int idx = i * 256 + tid;
        int r = idx >> 3, c = idx & 7;
        uint32_t dst = sbase + r * 128 + ((c ^ (r & 7)) << 4);
        cp_async16(dst, A + (((size_t)(m0 + r)) << 10) + kk + (c << 3));
    }
#pragma unroll
    for (int i = 0; i < 8; i++) {           // B: 256 rows x 8 chunks
        int idx = i * 256 + tid;
        int r = idx >> 3, c = idx & 7;
        int j = r >> 6, w = r & 63;
        int grow = (w < 32) ? (n0 * 128 + j * 32 + w)
                            : (1024 + n0 * 128 + j * 32 + (w - 32));
        uint32_t dst = bB + r * 128 + ((c ^ (r & 7)) << 4);
        cp_async16(dst, B + (((size_t)grow) << 10) + kk + (c << 3));
    }
}

__global__ void __launch_bounds__(256, 1) gemm_mma_kernel(
    const float* __restrict__ bz_g, const float* __restrict__ bh_g)
{
    extern __shared__ __align__(1024) char sm[];
    const uint32_t smem_base = smem_u32(sm);
    const int tid = threadIdx.x;
    const int lane = tid & 31;
    const int wid = tid >> 5;
    const int warp_m = wid >> 2;       // 0..1 : 64-row M half
    const int warp_j = wid & 3;        // 0..3 : 64-row N quarter (32 h)
    const int n0 = blockIdx.x;         // 0..7
    const int m0 = blockIdx.y * BM;

    float acc[4][8][4];
#pragma unroll
    for (int a = 0; a < 4; a++)
#pragma unroll
        for (int b = 0; b < 8; b++)
#pragma unroll
            for (int c = 0; c < 4; c++) acc[a][b][c] = 0.f;

    load_tile(0, smem_base + 0 * STAGE_BYTES, m0, n0, tid); CP_COMMIT();
    load_tile(1, smem_base + 1 * STAGE_BYTES, m0, n0, tid); CP_COMMIT();

    const int a_row = lane & 15;       // m within tile
    const int a_ch  = lane >> 4;       // k half
    const int b_row = lane & 7;        // n within tile
    const int b_kh  = (lane >> 3) & 1; // k half
    const int b_td  = lane >> 4;       // n8 tile within pair

    for (int kt = 0; kt < NTILES; ++kt) {
        if (kt) __syncthreads();       // stage (kt+2)%3 free to overwrite
        if (kt + 2 < NTILES)
            load_tile(kt + 2, smem_base + ((kt + 2) % STAGES) * STAGE_BYTES,
                      m0, n0, tid);
        CP_COMMIT();
        CP_WAIT2();                    // tile kt resident (this thread)
        __syncthreads();               // visible CTA-wide

        const uint32_t aB = smem_base + (kt % STAGES) * STAGE_BYTES;
        const uint32_t bB = aB + A_BYTES;
#pragma unroll
        for (int ks = 0; ks < 4; ks++) {
            uint32_t af[4][4];
#pragma unroll
            for (int mt = 0; mt < 4; mt++) {
                int r = warp_m * 64 + mt * 16 + a_row;
                int ch = (ks * 2 + a_ch) ^ (r & 7);
                LDSM_X4(af[mt][0], af[mt][1], af[mt][2], af[mt][3],
                        aB + r * 128 + ch * 16);
            }
            uint32_t bf[8][2];
#pragma unroll
            for (int tp = 0; tp < 4; tp++) {
                int tile = tp * 2 + b_td;
                int r = warp_j * 64 + tile * 8 + b_row;
                int ch = (ks * 2 + b_kh) ^ (r & 7);
                LDSM_X4(bf[tp * 2][0], bf[tp * 2][1],
                        bf[tp * 2 + 1][0], bf[tp * 2 + 1][1],
                        bB + r * 128 + ch * 16);
            }
#pragma unroll
            for (int mt = 0; mt < 4; mt++)
#pragma unroll
                for (int t = 0; t < 8; t++)
                    mma_bf16(acc[mt][t], af[mt], bf[t]);
        }
    }

    // ---------------- fused epilogue (in-register) ------------------------
    const int gr = lane >> 2;            // 0..7  (row in m16 tile)
    const int gc = (lane & 3) << 1;      // 0,2,4,6 (col pair)
#pragma unroll
    for (int t = 0; t < 4; t++) {
        int h = n0 * 128 + warp_j * 32 + t * 8 + gc;
        float bz0 = __ldg(bz_g + h),     bz1 = __ldg(bz_g + h + 1);
        float bh0 = __ldg(bh_g + h),     bh1 = __ldg(bh_g + h + 1);
#pragma unroll
        for (int mt = 0; mt < 4; mt++) {
            int r0 = m0 + warp_m * 64 + mt * 16 + gr;
            const float* ck = acc[mt][t];
            const float* ch = acc[mt][t + 4];
#pragma unroll
            for (int rr = 0; rr < 2; rr++) {
                float k0 = ck[rr * 2 + 0] + bz0;
                float k1 = ck[rr * 2 + 1] + bz1;
                float t0 = ch[rr * 2 + 0] + bh0;
                float t1 = ch[rr * 2 + 1] + bh1;
                float4 o;
                o.x = -softplus_f(k0);
                o.y = -softplus_f(-k0) + log_g_f(t0);
                o.z = -softplus_f(k1);
                o.w = -softplus_f(-k1) + log_g_f(t1);
                *(float4*)((float*)g_lcv +
                           (((size_t)(r0 + rr * 8)) * Hc + h) * 2) = o;
            }
        }
    }
}

// ===========================================================================
// chunked parallel scan (log-space):  lh <- logaddexp(lh + lc, lv)
// ===========================================================================
__global__ void scan_chunks_kernel()
{
    int g = blockIdx.x * blockDim.x + threadIdx.x;
    int bh = g & (BHc - 1);
    int c  = g >> 12;
    int b  = bh >> 10;
    int h  = bh & (Hc - 1);
    size_t base = ((size_t)b * Tc + (size_t)c * CLEN) * Hc + h;
    float A = 0.f, R = -INFINITY;
#pragma unroll 4
    for (int t = 0; t < CLEN; t++) {
        float2 v = g_lcv[base]; base += Hc;
        R = logaddexp_f(R + v.x, v.y);
        A += v.x;
    }
    g_A[g] = A;
    g_R[g] = R;
}

__global__ void scan_combine_kernel(const float* __restrict__ h0)
{
    int bh = blockIdx.x * blockDim.x + threadIdx.x;
    float lh = log_g_f(h0[bh]);
#pragma unroll
    for (int c = 0; c < NCHUNK; c++) {
        int idx = c * BHc + bh;
        g_hin[idx] = lh;
        lh = logaddexp_f(g_A[idx] + lh, g_R[idx]);
    }
}

__global__ void scan_final_kernel(float* __restrict__ out)
{
    int g = blockIdx.x * blockDim.x + threadIdx.x;
    int bh = g & (BHc - 1);
    int c  = g >> 12;
    int b  = bh >> 10;
    int h  = bh & (Hc - 1);
    size_t base = ((size_t)b * Tc + (size_t)c * CLEN) * Hc + h;
    float lh = g_hin[g];
#pragma unroll 4
    for (int t = 0; t < CLEN; t++) {
        float2 v = g_lcv[base];
        lh = logaddexp_f(lh + v.x, v.y);
        out[base] = __expf(lh);
        base += Hc;
    }
}

// ===========================================================================
extern "C" void kernel_launch(void* const* d_in, const int* in_sizes, int n_in,
                              void* d_out, int out_size)
{
    const float* x  = (const float*)d_in[0];
    const float* h0 = (const float*)d_in[1];
    const float* Wz = (const float*)d_in[2];
    const float* bz = (const float*)d_in[3];
    const float* Wh = (const float*)d_in[4];
    const float* bh = (const float*)d_in[5];
    float* out = (float*)d_out;

    cudaFuncSetAttribute(gemm_mma_kernel,
                         cudaFuncAttributeMaxDynamicSharedMemorySize, SMEM_TOTAL);

    split_x_kernel<<<16384, 256>>>((const float4*)x);
    split_w_kernel<<<2048, 256>>>((const float4*)Wz, (const float4*)Wh);

    dim3 ggrid(Hc / 128, (Bc * Tc) / BM);   // (8, 128)
    gemm_mma_kernel<<<ggrid, 256, SMEM_TOTAL>>>(bz, bh);

    scan_chunks_kernel<<<(NCHUNK * BHc) / 256, 256>>>();
    scan_combine_kernel<<<BHc / 256, 256>>>(h0);
    scan_final_kernel<<<(NCHUNK * BHc) / 256, 256>>>(out);
}

// round 7
// speedup vs baseline: 2.1900x; 1.0016x over previous
#include <cuda_runtime.h>
#include <cuda_bf16.h>
#include <math.h>
#include <stdint.h>

// ---------------- problem dims -------------------------------------------
#define Bc 4
#define Tc 4096
#define Dc 1024
#define Hc 1024
#define BHc (Bc * Hc)
#define NCHUNK 64
#define CLEN (Tc / NCHUNK)       // 64

// ---------------- GEMM geometry ------------------------------------------
#define BM 128
#define BN 256
#define NTILES 48                // K_total = 3072: hi*hi | lo*hi | hi*lo
#define STAGES 4
#define A_BYTES (BM * 128)       // 16384
#define B_BYTES (BN * 128)       // 32768
#define STAGE_BYTES (A_BYTES + B_BYTES)   // 49152
#define SMEM_TOTAL (STAGES * STAGE_BYTES) // 196608

// ---------------- scratch globals ----------------------------------------
__device__ __align__(1024) __nv_bfloat16 gx_hi[(size_t)Bc * Tc * Dc];
__device__ __align__(1024) __nv_bfloat16 gx_lo[(size_t)Bc * Tc * Dc];
__device__ __align__(1024) __nv_bfloat16 gw_hi[2048 * 1024];   // [Wz;Wh]
__device__ __align__(1024) __nv_bfloat16 gw_lo[2048 * 1024];
__device__ float2 g_lcv[(size_t)Bc * Tc * Hc];                 // (lc, lv)
__device__ float g_A[NCHUNK * BHc];
__device__ float g_R[NCHUNK * BHc];
__device__ float g_hin[NCHUNK * BHc];

// ---------------- PTX helpers --------------------------------------------
__device__ __forceinline__ uint32_t smem_u32(const void* p) {
    uint32_t a;
    asm("{ .reg .u64 t; cvta.to.shared.u64 t, %1; cvt.u32.u64 %0, t; }"
        : "=r"(a) : "l"(p));
    return a;
}
__device__ __forceinline__ void cp_async16(uint32_t dst, const void* src) {
    asm volatile("cp.async.cg.shared.global [%0], [%1], 16;"
                 :: "r"(dst), "l"(src) : "memory");
}
#define CP_COMMIT() asm volatile("cp.async.commit_group;" ::: "memory")
#define CP_WAIT_2() asm volatile("cp.async.wait_group 2;" ::: "memory")

#define LDSM_X4(r0, r1, r2, r3, addr) \
    asm volatile("ldmatrix.sync.aligned.m8n8.x4.shared.b16 {%0,%1,%2,%3}, [%4];" \
                 : "=r"(r0), "=r"(r1), "=r"(r2), "=r"(r3) : "r"(addr))

__device__ __forceinline__ void mma_bf16(float* c, const uint32_t* a,
                                         const uint32_t* b) {
    asm volatile(
        "mma.sync.aligned.m16n8k16.row.col.f32.bf16.bf16.f32 "
        "{%0,%1,%2,%3}, {%4,%5,%6,%7}, {%8,%9}, {%0,%1,%2,%3};"
        : "+f"(c[0]), "+f"(c[1]), "+f"(c[2]), "+f"(c[3])
        : "r"(a[0]), "r"(a[1]), "r"(a[2]), "r"(a[3]), "r"(b[0]), "r"(b[1]));
}

// ---------------- math helpers -------------------------------------------
__device__ __forceinline__ float softplus_f(float u) {
    return fmaxf(u, 0.f) + __logf(1.f + __expf(-fabsf(u)));
}
__device__ __forceinline__ float log_g_f(float v) {
    return (v >= 0.f) ? __logf(v + 0.5f) : -softplus_f(-v);
}
__device__ __forceinline__ float logaddexp_f(float a, float b) {
    float m = fmaxf(a, b);
    if (m == -INFINITY) return -INFINITY;
    return m + __logf(1.f + __expf(-fabsf(a - b)));
}
// lc = -softplus(k), lsig = -softplus(-k); share log1p(e^-|k|): 1 exp + 1 log.
__device__ __forceinline__ void lc_lsig(float k, float& lc, float& lsig) {
    float L = __logf(1.f + __expf(-fabsf(k)));
    lc   = -fmaxf(k, 0.f)  - L;
    lsig = -fmaxf(-k, 0.f) - L;
}

// ===========================================================================
// merged bf16 split kernel: x (4,194,304 float4) then [Wz;Wh] (524,288 float4)
// ===========================================================================
__global__ void split_kernel(const float4* __restrict__ x,
                             const float4* __restrict__ Wz,
                             const float4* __restrict__ Wh)
{
    int i = blockIdx.x * blockDim.x + threadIdx.x;   // < 4718592
    float4 v;
    uint2 *dhi, *dlo;
    if (i < 4194304) {
        v = x[i];
        dhi = (uint2*)gx_hi + i;
        dlo = (uint2*)gx_lo + i;
    } else {
        int j = i - 4194304;                          // 0..524287
        v = (j < 262144) ? Wz[j] : Wh[j - 262144];
        dhi = (uint2*)gw_hi + j;
        dlo = (uint2*)gw_lo + j;
    }
    union { __nv_bfloat16 b[4]; uint2 u; } ph, pl;
    ph.b[0] = __float2bfloat16_rn(v.x); ph.b[1] = __float2bfloat16_rn(v.y);
    ph.b[2] = __float2bfloat16_rn(v.z); ph.b[3] = __float2bfloat16_rn(v.w);
    pl.b[0] = __float2bfloat16_rn(v.x - __bfloat162float(ph.b[0]));
    pl.b[1] = __float2bfloat16_rn(v.y - __bfloat162float(ph.b[1]));
    pl.b[2] = __float2bfloat16_rn(v.z - __bfloat162float(ph.b[2]));
    pl.b[3] = __float2bfloat16_rn(v.w - __bfloat162float(ph.b[3]));
    *dhi = ph.u;
    *dlo = pl.u;
}

// ===========================================================================
// HMMA GEMM + fused log-space epilogue (see R6 layout comments).
// 4-stage cp.async pipeline, ONE __syncthreads per K-tile.
// ===========================================================================
__device__ __forceinline__ void load_tile(
    int kt, uint32_t sbase, int m0, int n0, int tid)
{
    int phase = kt >> 4;
    int kk = (kt & 15) << 6;
    const __nv_bfloat16* A = (phase == 1) ? gx_lo : gx_hi;
    const __nv_bfloat16* B = (phase == 2) ? gw_lo : gw_hi;
    uint32_t bB = sbase + A_BYTES;
#pragma unroll
    for (int i = 0; i < 4; i++) {           // A: 128 rows x 8 chunks
        int idx = i * 256 + tid;
        int r = idx >> 3, c = idx & 7;
        uint32_t dst = sbase + r * 128 + ((c ^ (r & 7)) << 4);
        cp_async16(dst, A + (((size_t)(m0 + r)) << 10) + kk + (c << 3));
    }
#pragma unroll
    for (int i = 0; i < 8; i++) {           // B: 256 rows x 8 chunks
        int idx = i * 256 + tid;
        int r = idx >> 3, c = idx & 7;
        int j = r >> 6, w = r & 63;
        int grow = (w < 32) ? (n0 * 128 + j * 32 + w)
                            : (1024 + n0 * 128 + j * 32 + (w - 32));
        uint32_t dst = bB + r * 128 + ((c ^ (r & 7)) << 4);
        cp_async16(dst, B + (((size_t)grow) << 10) + kk + (c << 3));
    }
}

__global__ void __launch_bounds__(256, 1) gemm_mma_kernel(
    const float* __restrict__ bz_g, const float* __restrict__ bh_g)
{
    extern __shared__ __align__(1024) char sm[];
    const uint32_t smem_base = smem_u32(sm);
    const int tid = threadIdx.x;
    const int lane = tid & 31;
    const int wid = tid >> 5;
    const int warp_m = wid >> 2;       // 0..1 : 64-row M half
    const int warp_j = wid & 3;        // 0..3 : 64-row N quarter (32 h)
    const int n0 = blockIdx.x;         // 0..7
    const int m0 = blockIdx.y * BM;

    float acc[4][8][4];
#pragma unroll
    for (int a = 0; a < 4; a++)
#pragma unroll
        for (int b = 0; b < 8; b++)
#pragma unroll
            for (int c = 0; c < 4; c++) acc[a][b][c] = 0.f;

    load_tile(0, smem_base + 0 * STAGE_BYTES, m0, n0, tid); CP_COMMIT();
    load_tile(1, smem_base + 1 * STAGE_BYTES, m0, n0, tid); CP_COMMIT();
    load_tile(2, smem_base + 2 * STAGE_BYTES, m0, n0, tid); CP_COMMIT();

    const int a_row = lane & 15;       // m within tile
    const int a_ch  = lane >> 4;       // k half
    const int b_row = lane & 7;        // n within tile
    const int b_kh  = (lane >> 3) & 1; // k half
    const int b_td  = lane >> 4;       // n8 tile within pair

    for (int kt = 0; kt < NTILES; ++kt) {
        CP_WAIT_2();                   // tile kt resident (this thread's part)
        __syncthreads();               // visible CTA-wide; prior compute done
        if (kt + 3 < NTILES)
            load_tile(kt + 3, smem_base + ((kt + 3) & 3) * STAGE_BYTES,
                      m0, n0, tid);
        CP_COMMIT();                   // empty group at tail keeps accounting

        const uint32_t aB = smem_base + (kt & 3) * STAGE_BYTES;
        const uint32_t bB = aB + A_BYTES;
#pragma unroll
        for (int ks = 0; ks < 4; ks++) {
            uint32_t af[4][4];
#pragma unroll
            for (int mt = 0; mt < 4; mt++) {
                int r = warp_m * 64 + mt * 16 + a_row;
                int ch = (ks * 2 + a_ch) ^ (r & 7);
                LDSM_X4(af[mt][0], af[mt][1], af[mt][2], af[mt][3],
                        aB + r * 128 + ch * 16);
            }
            uint32_t bf[8][2];
#pragma unroll
            for (int tp = 0; tp < 4; tp++) {
                int tile = tp * 2 + b_td;
                int r = warp_j * 64 + tile * 8 + b_row;
                int ch = (ks * 2 + b_kh) ^ (r & 7);
                LDSM_X4(bf[tp * 2][0], bf[tp * 2][1],
                        bf[tp * 2 + 1][0], bf[tp * 2 + 1][1],
                        bB + r * 128 + ch * 16);
            }
#pragma unroll
            for (int mt = 0; mt < 4; mt++)
#pragma unroll
                for (int t = 0; t < 8; t++)
                    mma_bf16(acc[mt][t], af[mt], bf[t]);
        }
    }

    // ---------------- fused epilogue (in-register) ------------------------
    const int gr = lane >> 2;            // 0..7  (row in m16 tile)
    const int gc = (lane & 3) << 1;      // 0,2,4,6 (col pair)
#pragma unroll
    for (int t = 0; t < 4; t++) {
        int h = n0 * 128 + warp_j * 32 + t * 8 + gc;
        float bz0 = __ldg(bz_g + h),     bz1 = __ldg(bz_g + h + 1);
        float bh0 = __ldg(bh_g + h),     bh1 = __ldg(bh_g + h + 1);
#pragma unroll
        for (int mt = 0; mt < 4; mt++) {
            int r0 = m0 + warp_m * 64 + mt * 16 + gr;
            const float* ck = acc[mt][t];
            const float* ch = acc[mt][t + 4];
#pragma unroll
            for (int rr = 0; rr < 2; rr++) {
                float k0 = ck[rr * 2 + 0] + bz0;
                float k1 = ck[rr * 2 + 1] + bz1;
                float t0 = ch[rr * 2 + 0] + bh0;
                float t1 = ch[rr * 2 + 1] + bh1;
                float4 o;
                float ls0, ls1;
                lc_lsig(k0, o.x, ls0);
                lc_lsig(k1, o.z, ls1);
                o.y = ls0 + log_g_f(t0);
                o.w = ls1 + log_g_f(t1);
                *(float4*)((float*)g_lcv +
                           (((size_t)(r0 + rr * 8)) * Hc + h) * 2) = o;
            }
        }
    }
}

// ===========================================================================
// chunked parallel scan (log-space):  lh <- logaddexp(lh + lc, lv)
// 2 chains per thread, float4 loads.
// ===========================================================================
__global__ void scan_chunks_kernel()
{
    int g = blockIdx.x * blockDim.x + threadIdx.x;   // < NCHUNK * BHc / 2
    int p = g & (BHc / 2 - 1);
    int c = g >> 11;
    int b = p >> 9;
    int h = (p & 511) << 1;
    size_t base = ((size_t)b * Tc + (size_t)c * CLEN) * Hc + h;
    float A0 = 0.f, R0 = -INFINITY, A1 = 0.f, R1 = -INFINITY;
#pragma unroll 8
    for (int t = 0; t < CLEN; t++) {
        float4 v = *(const float4*)&g_lcv[base]; base += Hc;
        R0 = logaddexp_f(R0 + v.x, v.y); A0 += v.x;
        R1 = logaddexp_f(R1 + v.z, v.w); A1 += v.z;
    }
    int idx = c * BHc + b * Hc + h;
    g_A[idx] = A0; g_A[idx + 1] = A1;
    g_R[idx] = R0; g_R[idx + 1] = R1;
}

__global__ void scan_combine_kernel(const float* __restrict__ h0)
{
    int bh = blockIdx.x * blockDim.x + threadIdx.x;
    float lh = log_g_f(h0[bh]);
#pragma unroll
    for (int c = 0; c < NCHUNK; c++) {
        int idx = c * BHc + bh;
        g_hin[idx] = lh;
        lh = logaddexp_f(g_A[idx] + lh, g_R[idx]);
    }
}

__global__ void scan_final_kernel(float* __restrict__ out)
{
    int g = blockIdx.x * blockDim.x + threadIdx.x;   // < NCHUNK * BHc / 2
    int p = g & (BHc / 2 - 1);
    int c = g >> 11;
    int b = p >> 9;
    int h = (p & 511) << 1;
    size_t base = ((size_t)b * Tc + (size_t)c * CLEN) * Hc + h;
    int idx = c * BHc + b * Hc + h;
    float lh0 = g_hin[idx], lh1 = g_hin[idx + 1];
#pragma unroll 8
    for (int t = 0; t < CLEN; t++) {
        float4 v = *(const float4*)&g_lcv[base];
        lh0 = logaddexp_f(lh0 + v.x, v.y);
        lh1 = logaddexp_f(lh1 + v.z, v.w);
        float2 o; o.x = __expf(lh0); o.y = __expf(lh1);
        *(float2*)&out[base] = o;
        base += Hc;
    }
}

// ===========================================================================
extern "C" void kernel_launch(void* const* d_in, const int* in_sizes, int n_in,
                              void* d_out, int out_size)
{
    const float* x  = (const float*)d_in[0];
    const float* h0 = (const float*)d_in[1];
    const float* Wz = (const float*)d_in[2];
    const float* bz = (const float*)d_in[3];
    const float* Wh = (const float*)d_in[4];
    const float* bh = (const float*)d_in[5];
    float* out = (float*)d_out;

    cudaFuncSetAttribute(gemm_mma_kernel,
                         cudaFuncAttributeMaxDynamicSharedMemorySize, SMEM_TOTAL);

    split_kernel<<<18432, 256>>>((const float4*)x, (const float4*)Wz,
                                 (const float4*)Wh);

    dim3 ggrid(Hc / 128, (Bc * Tc) / BM);   // (8, 128)
    gemm_mma_kernel<<<ggrid, 256, SMEM_TOTAL>>>(bz, bh);

    scan_chunks_kernel<<<(NCHUNK * BHc / 2) / 256, 256>>>();
    scan_combine_kernel<<<BHc / 256, 256>>>(h0);
    scan_final_kernel<<<(NCHUNK * BHc / 2) / 256, 256>>>(out);
}